// round 14
// baseline (speedup 1.0000x reference)
#include <cuda_runtime.h>
#include <cuda_bf16.h>
#include <stdint.h>

#define NB   32
#define MCH  16
#define HP   128
#define WPD  128
#define LTOT (126*126)      // 15876
#define OD   128
#define PD   144
#define CENTER 2.7416f      // E[chi_8]: analytic mean of pooled values

#define TILES_PER_N 32            // 32*512 slots per n
#define NTILES (NB*TILES_PER_N)   // 1024 windows of 512 patches
#define GRID 148                  // 1 CTA/SM persistent
#define PAD_PER_N 508             // 16384 - 15876
#define NPTASK (NB*HP)            // 4096 pool row-tasks

#define WS 152                    // W smem row stride (halves)
#define WIN_BYTES 32768           // 8 rows x 128 w x 16 ch x 2B
#define OFF_ZERO (2*WIN_BYTES)
#define OFF_W    (OFF_ZERO + 16)
#define OFF_POOL (OFF_W + OD*WS*2)
#define SMEM_BYTES (OFF_POOL + 128*18*2)

// ---- static device scratch (no allocation) ----
__device__ __align__(32) __nv_bfloat16 g_pooled[NB*HP*WPD*MCH];  // channel-last, centered bf16
__device__ float g_const2[OD];   // b + CENTER * sum_k W
__device__ float g_acc[NB*OD];
__device__ int   g_ready[NB];    // pooled rows complete per batch

// ---- helpers ----
__device__ __forceinline__ uint32_t smem_u32(const void* p) {
    uint32_t a;
    asm("{ .reg .u64 t; cvta.to.shared.u64 t, %1; cvt.u32.u64 %0, t; }" : "=r"(a) : "l"(p));
    return a;
}
__device__ __forceinline__ void ldsm_x4(uint32_t* r, uint32_t addr) {
    asm volatile("ldmatrix.sync.aligned.m8n8.x4.shared.b16 {%0,%1,%2,%3}, [%4];"
        : "=r"(r[0]), "=r"(r[1]), "=r"(r[2]), "=r"(r[3]) : "r"(addr));
}
__device__ __forceinline__ void mma16816(float* c, const uint32_t* a, uint32_t b0, uint32_t b1) {
    asm volatile(
        "mma.sync.aligned.m16n8k16.row.col.f32.bf16.bf16.f32 "
        "{%0,%1,%2,%3}, {%4,%5,%6,%7}, {%8,%9}, {%0,%1,%2,%3};\n"
        : "+f"(c[0]), "+f"(c[1]), "+f"(c[2]), "+f"(c[3])
        : "r"(a[0]), "r"(a[1]), "r"(a[2]), "r"(a[3]), "r"(b0), "r"(b1));
}
__device__ __forceinline__ void cp16(uint32_t dst, const void* src) {
    asm volatile("cp.async.cg.shared.global [%0], [%1], 16;" :: "r"(dst), "l"(src) : "memory");
}
__device__ __forceinline__ void bar_gemm() { asm volatile("bar.sync 2, 128;" ::: "memory"); }
__device__ __forceinline__ void bar_pool() { asm volatile("bar.sync 1, 128;" ::: "memory"); }
__device__ __forceinline__ void wait_ready(int n) {
    unsigned r;
    asm volatile("ld.acquire.gpu.u32 %0, [%1];" : "=r"(r) : "l"((const unsigned*)&g_ready[n]));
    while (r < 128u) {
        __nanosleep(128);
        asm volatile("ld.acquire.gpu.u32 %0, [%1];" : "=r"(r) : "l"((const unsigned*)&g_ready[n]));
    }
}

// ---- prep: fold bias + zero accumulators/flags ----
__global__ void prep_kernel(const float* __restrict__ w, const float* __restrict__ b) {
    int tid = threadIdx.x;
    for (int i = tid; i < NB*OD; i += blockDim.x) g_acc[i] = 0.f;
    if (tid < NB) g_ready[tid] = 0;
    if (tid < OD) {
        float s = 0.f;
        #pragma unroll 4
        for (int k = 0; k < PD; k++) s += w[tid*PD + k];
        g_const2[tid] = b[tid] + CENTER * s;
    }
}

// ---- fused persistent kernel: warps 0-3 GEMM consumer, warps 4-7 pool producer ----
__global__ __launch_bounds__(256, 1) void fused_kernel(const float* __restrict__ x,
                                                       const float* __restrict__ w) {
    extern __shared__ __align__(16) unsigned char smem[];
    const uint32_t aS = smem_u32(smem);
    const uint32_t aZ = aS + OFF_ZERO;
    const uint32_t aW = aS + OFF_W;
    const int tid = threadIdx.x;

    if (tid < 128) {
        // ================= GEMM consumer (warps 0-3) =================
        const int warp = tid >> 5, lane = tid & 31;
        const int g = lane >> 2, th = lane & 3;
        const int obase = warp * 32;
        const uint32_t hf16 = ((lane >> 3) & 1) * 16;
        const int rowoff = (lane & 7) + ((lane >> 4) << 3);

        // stage W (persistent region): column k' = shift*16 + channel
        {
            __nv_bfloat16* sW = (__nv_bfloat16*)(smem + OFF_W);
            for (int t = tid; t < OD*PD; t += 128) {
                int o = t / PD, kp = t - o*PD;
                int sft = kp >> 4, c = kp & 15;
                sW[o*WS + kp] = __float2bfloat16(w[o*PD + c*9 + sft]);
            }
        }
        if (tid == 0) *(uint4*)(smem + OFF_ZERO) = make_uint4(0u, 0u, 0u, 0u);
        float cst[2][2];
        #pragma unroll
        for (int mt = 0; mt < 2; mt++) {
            cst[mt][0] = g_const2[obase + mt*16 + g];
            cst[mt][1] = g_const2[obase + mt*16 + g + 8];
        }
        bar_gemm();

        // staging identity: 2 chunks per thread per row
        const uint32_t c0 = tid, c1 = tid + 128;
        const uint32_t sd0 = (c0*16u) ^ ((c0 & 8u) << 1);
        const uint32_t sd1 = (c1*16u) ^ ((c1 & 8u) << 1);

        const uint32_t aA0 = aW + (obase + (lane & 15)) * (WS*2) + (lane >> 4) * 16;

        // prologue: stage first window
        {
            if (tid == 0) wait_ready(blockIdx.x >> 5);
            bar_gemm();
            int n = blockIdx.x >> 5, tile = blockIdx.x & 31;
            int pi0 = (tile << 9) / 126;
            #pragma unroll
            for (int r = 0; r < 8; r++) {
                int grow = pi0 + r; if (grow > 127) grow = 127;
                const __nv_bfloat16* rp = g_pooled + (size_t)(n*HP + grow)*2048;
                cp16(aS + r*4096 + sd0, rp + c0*8);
                cp16(aS + r*4096 + sd1, rp + c1*8);
            }
            asm volatile("cp.async.commit_group;" ::: "memory");
        }

        uint32_t boff = 0;
        for (int idx = blockIdx.x; idx < NTILES; idx += GRID) {
            asm volatile("cp.async.wait_group 0;" ::: "memory");
            bar_gemm();

            const int n = idx >> 5, tile = idx & 31;
            const int l0 = tile << 9;
            const int pi0 = l0 / 126;
            const uint32_t wb = aS + boff;

            float rs[2][2] = {{0.f, 0.f}, {0.f, 0.f}};

            #pragma unroll
            for (int sub = 0; sub < 4; sub++) {
                uint32_t pbv[8]; bool pv[8];
                #pragma unroll
                for (int p = 0; p < 8; p++) {
                    int lg = l0 + sub*128 + p*16 + rowoff;
                    unsigned pi = (unsigned)lg / 126u;
                    unsigned pj = (unsigned)lg - pi*126u;
                    pv[p] = lg < LTOT;
                    pbv[p] = (pi - (unsigned)pi0)*4096u + pj*32u + hf16;
                }
                float acc[2][16][4];
                #pragma unroll
                for (int mt = 0; mt < 2; mt++)
                    #pragma unroll
                    for (int nf = 0; nf < 16; nf++)
                        #pragma unroll
                        for (int q = 0; q < 4; q++) acc[mt][nf][q] = 0.f;

                #pragma unroll
                for (int s = 0; s < 9; s++) {
                    const int ki = s / 3, kj = s - 3*ki;
                    const uint32_t ko = ki*4096u + kj*32u;
                    uint32_t A0[4], A1[4];
                    ldsm_x4(A0, aA0 + s*32);
                    ldsm_x4(A1, aA0 + 16*(WS*2) + s*32);
                    #pragma unroll
                    for (int p = 0; p < 8; p++) {
                        uint32_t rel = pbv[p] + ko;
                        rel ^= (rel >> 3) & 0x10u;
                        uint32_t addr = pv[p] ? (wb + rel) : aZ;
                        uint32_t bb[4];
                        ldsm_x4(bb, addr);
                        mma16816(acc[0][2*p],   A0, bb[0], bb[1]);
                        mma16816(acc[0][2*p+1], A0, bb[2], bb[3]);
                        mma16816(acc[1][2*p],   A1, bb[0], bb[1]);
                        mma16816(acc[1][2*p+1], A1, bb[2], bb[3]);
                    }
                }
                // branch-free celu sums (pad corrected analytically in norm)
                #pragma unroll
                for (int mt = 0; mt < 2; mt++) {
                    float s0 = 0.f, e0 = 0.f, s1 = 0.f, e1 = 0.f;
                    #pragma unroll
                    for (int nf = 0; nf < 16; nf++) {
                        float v0 = acc[mt][nf][0] + cst[mt][0];
                        float v1 = acc[mt][nf][1] + cst[mt][0];
                        float u0 = acc[mt][nf][2] + cst[mt][1];
                        float u1 = acc[mt][nf][3] + cst[mt][1];
                        s0 += fmaxf(v0, 0.f) + fmaxf(v1, 0.f);
                        e0 += __expf(fminf(v0, 0.f)) + __expf(fminf(v1, 0.f));
                        s1 += fmaxf(u0, 0.f) + fmaxf(u1, 0.f);
                        e1 += __expf(fminf(u0, 0.f)) + __expf(fminf(u1, 0.f));
                    }
                    rs[mt][0] += s0 + e0;
                    rs[mt][1] += s1 + e1;
                }
            }

            // stage next window (spin only gates future work, current already done)
            int nidx = idx + GRID;
            if (nidx < NTILES) {
                if (tid == 0) wait_ready(nidx >> 5);
                bar_gemm();
                int nn = nidx >> 5, nt = nidx & 31;
                int npi0 = (nt << 9) / 126;
                uint32_t d = aS + (boff ^ WIN_BYTES);
                #pragma unroll
                for (int r = 0; r < 8; r++) {
                    int grow = npi0 + r; if (grow > 127) grow = 127;
                    const __nv_bfloat16* rp = g_pooled + (size_t)(nn*HP + grow)*2048;
                    cp16(d + r*4096 + sd0, rp + c0*8);
                    cp16(d + r*4096 + sd1, rp + c1*8);
                }
            }
            asm volatile("cp.async.commit_group;" ::: "memory");

            #pragma unroll
            for (int mt = 0; mt < 2; mt++) {
                float s0 = rs[mt][0], s1 = rs[mt][1];
                #pragma unroll
                for (int off = 1; off < 4; off <<= 1) {
                    s0 += __shfl_xor_sync(0xffffffffu, s0, off);
                    s1 += __shfl_xor_sync(0xffffffffu, s1, off);
                }
                if (th == 0) {
                    atomicAdd(&g_acc[n*OD + obase + mt*16 + g],     s0);
                    atomicAdd(&g_acc[n*OD + obase + mt*16 + g + 8], s1);
                }
            }
            boff ^= WIN_BYTES;
        }
    } else {
        // ================= pool producer (warps 4-7) =================
        __nv_bfloat16* s2 = (__nv_bfloat16*)(smem + OFF_POOL);
        const int t2 = tid - 128;
        const int wp = t2 & 63;        // w-pair
        const int mh = t2 >> 6;        // channel half

        for (int task = blockIdx.x; task < NPTASK; task += GRID) {
            const int n = task >> 7, h = task & 127;
            const float* xb = x + (size_t)n*8*4*65536 + 2*h*256 + 4*wp;
            #pragma unroll
            for (int q = 0; q < 8; q++) {
                int mc = mh*8 + q;
                int dp = mc >> 3, c = mc & 7;
                const float* base = xb + (size_t)(c*4 + 2*dp)*65536;
                float4 r0 = *(const float4*)(base);
                float4 r1 = *(const float4*)(base + 256);
                float4 r2 = *(const float4*)(base + 65536);
                float4 r3 = *(const float4*)(base + 65536 + 256);
                float a0 = r0.x*r0.x + r0.y*r0.y + r1.x*r1.x + r1.y*r1.y
                         + r2.x*r2.x + r2.y*r2.y + r3.x*r3.x + r3.y*r3.y;
                float a1 = r0.z*r0.z + r0.w*r0.w + r1.z*r1.z + r1.w*r1.w
                         + r2.z*r2.z + r2.w*r2.w + r3.z*r3.z + r3.w*r3.w;
                s2[(2*wp)*18 + mc]   = __float2bfloat16(sqrtf(a0) - CENTER);
                s2[(2*wp+1)*18 + mc] = __float2bfloat16(sqrtf(a1) - CENTER);
            }
            bar_pool();
            // channel-last writeback: thread t2 -> row w = t2 (32 contiguous bytes)
            {
                uint32_t v[8];
                #pragma unroll
                for (int k = 0; k < 8; k++)
                    v[k] = *(const uint32_t*)(s2 + t2*18 + 2*k);
                __nv_bfloat16* dst = g_pooled + (size_t)((n*HP + h)*WPD + t2)*MCH;
                *(uint4*)(dst)     = make_uint4(v[0], v[1], v[2], v[3]);
                *(uint4*)(dst + 8) = make_uint4(v[4], v[5], v[6], v[7]);
            }
            __threadfence();
            bar_pool();
            if (t2 == 0) atomicAdd(&g_ready[n], 1);
        }
    }
}

// ---- pad-correct + mean + clamped L2 normalize ----
__global__ void norm_kernel(float* __restrict__ out) {
    int n = blockIdx.x, o = threadIdx.x;
    float cst = g_const2[o];
    float padv = fmaxf(cst, 0.f) + __expf(fminf(cst, 0.f));  // per padded slot (no -1)
    float a = (g_acc[n*OD + o] - (float)PAD_PER_N * padv - (float)LTOT) * (1.f / (float)LTOT);
    float ss = a * a;
    __shared__ float red[4];
    int lane = o & 31, w = o >> 5;
    #pragma unroll
    for (int off = 16; off; off >>= 1) ss += __shfl_xor_sync(0xffffffffu, ss, off);
    if (lane == 0) red[w] = ss;
    __syncthreads();
    float norm = sqrtf(red[0] + red[1] + red[2] + red[3]);
    out[n*OD + o] = a / fmaxf(norm, 1e-6f);
}

// ---- launch ----
extern "C" void kernel_launch(void* const* d_in, const int* in_sizes, int n_in,
                              void* d_out, int out_size) {
    const float* x = (const float*)d_in[0];
    const float* w = (const float*)d_in[1];
    const float* b = (const float*)d_in[2];
    float* out = (float*)d_out;

    prep_kernel<<<1, 256>>>(w, b);
    cudaFuncSetAttribute(fused_kernel, cudaFuncAttributeMaxDynamicSharedMemorySize, SMEM_BYTES);
    fused_kernel<<<GRID, 256, SMEM_BYTES>>>(x, w);
    norm_kernel<<<NB, 128>>>(out);
}

// round 15
// speedup vs baseline: 1.1875x; 1.1875x over previous
#include <cuda_runtime.h>
#include <cuda_bf16.h>
#include <stdint.h>

#define NB   32
#define MCH  16
#define HP   128
#define WPD  128
#define LTOT (126*126)      // 15876
#define OD   128
#define PD   144
#define CENTER 2.7416f      // E[chi_8]: analytic mean of pooled values

#define TILES_PER_N 32            // 32*512 slots per n
#define NTILES (NB*TILES_PER_N)   // 1024 windows of 512 patches
#define GRID 148                  // 1 CTA/SM persistent
#define PAD_PER_N 508             // 16384 - 15876
#define NPTASK (NB*HP)            // 4096 pool row-tasks

#define WS 152                    // W smem row stride (halves)
#define WIN_BYTES 32768           // 8 rows x 128 w x 16 ch x 2B
#define OFF_ZERO (2*WIN_BYTES)
#define OFF_W    (OFF_ZERO + 16)
#define OFF_POOL (OFF_W + OD*WS*2)
#define SMEM_BYTES (OFF_POOL + 128*18*2)

// ---- static device scratch (no allocation) ----
__device__ __align__(32) __nv_bfloat16 g_pooled[NB*HP*WPD*MCH];  // channel-last, centered bf16
__device__ float g_const2[OD];   // b + CENTER * sum_k W
__device__ float g_acc[NB*OD];
__device__ int   g_ready[NB];    // pooled rows complete per batch

// ---- helpers ----
__device__ __forceinline__ uint32_t smem_u32(const void* p) {
    uint32_t a;
    asm("{ .reg .u64 t; cvta.to.shared.u64 t, %1; cvt.u32.u64 %0, t; }" : "=r"(a) : "l"(p));
    return a;
}
__device__ __forceinline__ void ldsm_x4(uint32_t* r, uint32_t addr) {
    asm volatile("ldmatrix.sync.aligned.m8n8.x4.shared.b16 {%0,%1,%2,%3}, [%4];"
        : "=r"(r[0]), "=r"(r[1]), "=r"(r[2]), "=r"(r[3]) : "r"(addr));
}
__device__ __forceinline__ void mma16816(float* c, const uint32_t* a, uint32_t b0, uint32_t b1) {
    asm volatile(
        "mma.sync.aligned.m16n8k16.row.col.f32.bf16.bf16.f32 "
        "{%0,%1,%2,%3}, {%4,%5,%6,%7}, {%8,%9}, {%0,%1,%2,%3};\n"
        : "+f"(c[0]), "+f"(c[1]), "+f"(c[2]), "+f"(c[3])
        : "r"(a[0]), "r"(a[1]), "r"(a[2]), "r"(a[3]), "r"(b0), "r"(b1));
}
__device__ __forceinline__ void cp16(uint32_t dst, const void* src) {
    asm volatile("cp.async.cg.shared.global [%0], [%1], 16;" :: "r"(dst), "l"(src) : "memory");
}
__device__ __forceinline__ void bar_gemm() { asm volatile("bar.sync 2, 256;" ::: "memory"); }
__device__ __forceinline__ void bar_pool() { asm volatile("bar.sync 1, 128;" ::: "memory"); }
__device__ __forceinline__ void wait_ready(int n) {
    unsigned r;
    asm volatile("ld.acquire.gpu.u32 %0, [%1];" : "=r"(r) : "l"((const unsigned*)&g_ready[n]));
    while (r < 128u) {
        __nanosleep(128);
        asm volatile("ld.acquire.gpu.u32 %0, [%1];" : "=r"(r) : "l"((const unsigned*)&g_ready[n]));
    }
}

// ---- prep (parallel): block o sums W row o, zeros its g_acc slice ----
__global__ void prep_kernel(const float* __restrict__ w, const float* __restrict__ b) {
    int o = blockIdx.x, t = threadIdx.x;   // 128 blocks x 32 threads
    g_acc[o*32 + t] = 0.f;
    if (o < NB && t == 0) g_ready[o] = 0;
    float s = 0.f;
    for (int k = t; k < PD; k += 32) s += w[o*PD + k];
    #pragma unroll
    for (int off = 16; off; off >>= 1) s += __shfl_xor_sync(0xffffffffu, s, off);
    if (t == 0) g_const2[o] = b[o] + CENTER * s;
}

// ---- fused persistent kernel: warps 0-7 GEMM consumer, warps 8-11 pool producer ----
__global__ __launch_bounds__(384, 1) void fused_kernel(const float* __restrict__ x,
                                                       const float* __restrict__ w) {
    extern __shared__ __align__(16) unsigned char smem[];
    const uint32_t aS = smem_u32(smem);
    const uint32_t aZ = aS + OFF_ZERO;
    const uint32_t aW = aS + OFF_W;
    const int tid = threadIdx.x;

    if (tid < 256) {
        // ================= GEMM consumer (warps 0-7, R13 datapath) =================
        const int warp = tid >> 5, lane = tid & 31;
        const int wm = warp & 3, wn = warp >> 2;   // 4 o-tiles x 2 l-halves
        const int g = lane >> 2, th = lane & 3;
        const int obase = wm * 32;
        const int lbase = wn * 64;
        const uint32_t hf16 = ((lane >> 3) & 1) * 16;
        const int rowoff = (lane & 7) + ((lane >> 4) << 3);

        // stage W (persistent): column k' = shift*16 + channel
        {
            __nv_bfloat16* sW = (__nv_bfloat16*)(smem + OFF_W);
            for (int t = tid; t < OD*PD; t += 256) {
                int o = t / PD, kp = t - o*PD;
                int sft = kp >> 4, c = kp & 15;
                sW[o*WS + kp] = __float2bfloat16(w[o*PD + c*9 + sft]);
            }
        }
        if (tid == 0) *(uint4*)(smem + OFF_ZERO) = make_uint4(0u, 0u, 0u, 0u);
        float cst[2][2];
        #pragma unroll
        for (int mt = 0; mt < 2; mt++) {
            cst[mt][0] = g_const2[obase + mt*16 + g];
            cst[mt][1] = g_const2[obase + mt*16 + g + 8];
        }
        bar_gemm();

        const uint32_t aA0 = aW + (obase + (lane & 15)) * (WS*2) + (lane >> 4) * 16;
        // staging identity: chunk tid of 2048 per window (8 rows x 256 chunks? -> 1 per row)
        const uint32_t sdst = (uint32_t)(tid*16) ^ (uint32_t)((tid & 8) << 1);
        const __nv_bfloat16* srcb = g_pooled + tid*8;

        // prologue: stage first window
        {
            if (tid == 0) wait_ready(blockIdx.x >> 5);
            bar_gemm();
            int n = blockIdx.x >> 5, tile = blockIdx.x & 31;
            int pi0 = (tile << 9) / 126;
            #pragma unroll
            for (int r = 0; r < 8; r++) {
                int grow = pi0 + r; if (grow > 127) grow = 127;
                cp16(aS + r*4096 + sdst, srcb + (size_t)(n*HP + grow)*2048);
            }
            asm volatile("cp.async.commit_group;" ::: "memory");
        }

        uint32_t boff = 0;
        for (int idx = blockIdx.x; idx < NTILES; idx += GRID) {
            asm volatile("cp.async.wait_group 0;" ::: "memory");
            bar_gemm();   // current window ready; previous readers done

            const int n = idx >> 5, tile = idx & 31;
            const int l0 = tile << 9;
            const int pi0 = l0 / 126;
            const uint32_t wb = aS + boff;

            // stage next window BEFORE compute (overlap)
            int nidx = idx + GRID;
            if (nidx < NTILES) {
                if (tid == 0) wait_ready(nidx >> 5);
                bar_gemm();
                int nn = nidx >> 5, nt = nidx & 31;
                int npi0 = (nt << 9) / 126;
                uint32_t d = aS + (boff ^ WIN_BYTES);
                #pragma unroll
                for (int r = 0; r < 8; r++) {
                    int grow = npi0 + r; if (grow > 127) grow = 127;
                    cp16(d + r*4096 + sdst, srcb + (size_t)(nn*HP + grow)*2048);
                }
            }
            asm volatile("cp.async.commit_group;" ::: "memory");

            float rs[2][2] = {{0.f, 0.f}, {0.f, 0.f}};

            #pragma unroll
            for (int sub = 0; sub < 4; sub++) {
                uint32_t pbv[4]; bool pv[4];
                #pragma unroll
                for (int p = 0; p < 4; p++) {
                    int lg = l0 + sub*128 + lbase + p*16 + rowoff;
                    unsigned pi = (unsigned)lg / 126u;
                    unsigned pj = (unsigned)lg - pi*126u;
                    pv[p] = lg < LTOT;
                    pbv[p] = (pi - (unsigned)pi0)*4096u + pj*32u + hf16;
                }
                float acc[2][8][4];
                #pragma unroll
                for (int mt = 0; mt < 2; mt++)
                    #pragma unroll
                    for (int nf = 0; nf < 8; nf++)
                        #pragma unroll
                        for (int q = 0; q < 4; q++) acc[mt][nf][q] = 0.f;

                #pragma unroll
                for (int s = 0; s < 9; s++) {
                    const int ki = s / 3, kj = s - 3*ki;
                    const uint32_t ko = ki*4096u + kj*32u;
                    uint32_t A0[4], A1[4];
                    ldsm_x4(A0, aA0 + s*32);
                    ldsm_x4(A1, aA0 + 16*(WS*2) + s*32);
                    #pragma unroll
                    for (int p = 0; p < 4; p++) {
                        uint32_t rel = pbv[p] + ko;
                        rel ^= (rel >> 3) & 0x10u;      // bank de-conflict swizzle
                        uint32_t addr = pv[p] ? (wb + rel) : aZ;
                        uint32_t bb[4];
                        ldsm_x4(bb, addr);
                        mma16816(acc[0][2*p],   A0, bb[0], bb[1]);
                        mma16816(acc[0][2*p+1], A0, bb[2], bb[3]);
                        mma16816(acc[1][2*p],   A1, bb[0], bb[1]);
                        mma16816(acc[1][2*p+1], A1, bb[2], bb[3]);
                    }
                }
                // branch-free celu sums (pad corrected analytically in norm)
                #pragma unroll
                for (int mt = 0; mt < 2; mt++) {
                    float s0 = 0.f, e0 = 0.f, s1 = 0.f, e1 = 0.f;
                    #pragma unroll
                    for (int nf = 0; nf < 8; nf++) {
                        float v0 = acc[mt][nf][0] + cst[mt][0];
                        float v1 = acc[mt][nf][1] + cst[mt][0];
                        float u0 = acc[mt][nf][2] + cst[mt][1];
                        float u1 = acc[mt][nf][3] + cst[mt][1];
                        s0 += fmaxf(v0, 0.f) + fmaxf(v1, 0.f);
                        e0 += __expf(fminf(v0, 0.f)) + __expf(fminf(v1, 0.f));
                        s1 += fmaxf(u0, 0.f) + fmaxf(u1, 0.f);
                        e1 += __expf(fminf(u0, 0.f)) + __expf(fminf(u1, 0.f));
                    }
                    rs[mt][0] += s0 + e0;
                    rs[mt][1] += s1 + e1;
                }
            }

            #pragma unroll
            for (int mt = 0; mt < 2; mt++) {
                float s0 = rs[mt][0], s1 = rs[mt][1];
                #pragma unroll
                for (int off = 1; off < 4; off <<= 1) {
                    s0 += __shfl_xor_sync(0xffffffffu, s0, off);
                    s1 += __shfl_xor_sync(0xffffffffu, s1, off);
                }
                if (th == 0) {
                    atomicAdd(&g_acc[n*OD + obase + mt*16 + g],     s0);
                    atomicAdd(&g_acc[n*OD + obase + mt*16 + g + 8], s1);
                }
            }
            boff ^= WIN_BYTES;
        }
    } else {
        // ================= pool producer (warps 8-11) =================
        __nv_bfloat16* s2 = (__nv_bfloat16*)(smem + OFF_POOL);
        const int t2 = tid - 256;
        const int wp = t2 & 63;        // w-pair
        const int mh = t2 >> 6;        // channel half

        for (int task = blockIdx.x; task < NPTASK; task += GRID) {
            const int n = task >> 7, h = task & 127;
            const float* xb = x + (size_t)n*8*4*65536 + 2*h*256 + 4*wp;
            #pragma unroll
            for (int q = 0; q < 8; q++) {
                int mc = mh*8 + q;
                int dp = mc >> 3, c = mc & 7;
                const float* base = xb + (size_t)(c*4 + 2*dp)*65536;
                float4 r0 = *(const float4*)(base);
                float4 r1 = *(const float4*)(base + 256);
                float4 r2 = *(const float4*)(base + 65536);
                float4 r3 = *(const float4*)(base + 65536 + 256);
                float a0 = r0.x*r0.x + r0.y*r0.y + r1.x*r1.x + r1.y*r1.y
                         + r2.x*r2.x + r2.y*r2.y + r3.x*r3.x + r3.y*r3.y;
                float a1 = r0.z*r0.z + r0.w*r0.w + r1.z*r1.z + r1.w*r1.w
                         + r2.z*r2.z + r2.w*r2.w + r3.z*r3.z + r3.w*r3.w;
                s2[(2*wp)*18 + mc]   = __float2bfloat16(sqrtf(a0) - CENTER);
                s2[(2*wp+1)*18 + mc] = __float2bfloat16(sqrtf(a1) - CENTER);
            }
            bar_pool();
            // channel-last writeback: thread t2 -> row w = t2 (32 contiguous bytes)
            {
                uint32_t v[8];
                #pragma unroll
                for (int k = 0; k < 8; k++)
                    v[k] = *(const uint32_t*)(s2 + t2*18 + 2*k);
                __nv_bfloat16* dst = g_pooled + (size_t)((n*HP + h)*WPD + t2)*MCH;
                *(uint4*)(dst)     = make_uint4(v[0], v[1], v[2], v[3]);
                *(uint4*)(dst + 8) = make_uint4(v[4], v[5], v[6], v[7]);
            }
            __threadfence();
            bar_pool();
            if (t2 == 0) atomicAdd(&g_ready[n], 1);
        }
    }
}

// ---- pad-correct + mean + clamped L2 normalize ----
__global__ void norm_kernel(float* __restrict__ out) {
    int n = blockIdx.x, o = threadIdx.x;
    float cst = g_const2[o];
    float padv = fmaxf(cst, 0.f) + __expf(fminf(cst, 0.f));  // per padded slot (no -1)
    float a = (g_acc[n*OD + o] - (float)PAD_PER_N * padv - (float)LTOT) * (1.f / (float)LTOT);
    float ss = a * a;
    __shared__ float red[4];
    int lane = o & 31, w = o >> 5;
    #pragma unroll
    for (int off = 16; off; off >>= 1) ss += __shfl_xor_sync(0xffffffffu, ss, off);
    if (lane == 0) red[w] = ss;
    __syncthreads();
    float norm = sqrtf(red[0] + red[1] + red[2] + red[3]);
    out[n*OD + o] = a / fmaxf(norm, 1e-6f);
}

// ---- launch ----
extern "C" void kernel_launch(void* const* d_in, const int* in_sizes, int n_in,
                              void* d_out, int out_size) {
    const float* x = (const float*)d_in[0];
    const float* w = (const float*)d_in[1];
    const float* b = (const float*)d_in[2];
    float* out = (float*)d_out;

    prep_kernel<<<128, 32>>>(w, b);
    cudaFuncSetAttribute(fused_kernel, cudaFuncAttributeMaxDynamicSharedMemorySize, SMEM_BYTES);
    fused_kernel<<<GRID, 384, SMEM_BYTES>>>(x, w);
    norm_kernel<<<NB, 128>>>(out);
}

// round 16
// speedup vs baseline: 1.9956x; 1.6805x over previous
#include <cuda_runtime.h>
#include <cuda_bf16.h>
#include <stdint.h>

#define NB   32
#define MCH  16
#define HP   128
#define WPD  128
#define LTOT (126*126)      // 15876
#define OD   128
#define PD   144
#define CENTER 2.7416f      // E[chi_8]: analytic mean of pooled values

#define TILE_L 512
#define TILES_PER_N 32            // 32*512 = 16384 slots per n
#define NTILES (NB*TILES_PER_N)   // 1024
#define GRID_GEMM 148             // 1 CTA/SM persistent
#define PAD_PER_N 508             // 16384 - 15876
#define NPTASK (NB*HP)            // 4096 pool row-tasks

#define WS 152                    // W smem row stride (halves) for A-frag ldmatrix
#define WIN_ROWS 8
#define WIN_BYTES (WIN_ROWS*4096) // 32768: 8 rows x 128 w x 16 ch x 2B
#define SMEM_BYTES (2*WIN_BYTES + 16)

// ---- static device scratch (no allocation) ----
__device__ __align__(32) __nv_bfloat16 g_pooled[NB*HP*WPD*MCH];  // channel-last, centered bf16
__device__ float g_const2[OD];   // b + CENTER * sum_k W
__device__ float g_acc[NB*OD];

// ---- helpers ----
__device__ __forceinline__ uint32_t smem_u32(const void* p) {
    uint32_t a;
    asm("{ .reg .u64 t; cvta.to.shared.u64 t, %1; cvt.u32.u64 %0, t; }" : "=r"(a) : "l"(p));
    return a;
}
__device__ __forceinline__ void ldsm_x4(uint32_t* r, uint32_t addr) {
    asm volatile("ldmatrix.sync.aligned.m8n8.x4.shared.b16 {%0,%1,%2,%3}, [%4];"
        : "=r"(r[0]), "=r"(r[1]), "=r"(r[2]), "=r"(r[3]) : "r"(addr));
}
__device__ __forceinline__ void mma16816(float* c, const uint32_t* a, uint32_t b0, uint32_t b1) {
    asm volatile(
        "mma.sync.aligned.m16n8k16.row.col.f32.bf16.bf16.f32 "
        "{%0,%1,%2,%3}, {%4,%5,%6,%7}, {%8,%9}, {%0,%1,%2,%3};\n"
        : "+f"(c[0]), "+f"(c[1]), "+f"(c[2]), "+f"(c[3])
        : "r"(a[0]), "r"(a[1]), "r"(a[2]), "r"(a[3]), "r"(b0), "r"(b1));
}
__device__ __forceinline__ void cp16(uint32_t dst, const void* src) {
    asm volatile("cp.async.cg.shared.global [%0], [%1], 16;" :: "r"(dst), "l"(src) : "memory");
}

// ---- prep (parallel): block o sums W row o, zeros its g_acc slice ----
__global__ void prep_kernel(const float* __restrict__ w, const float* __restrict__ b) {
    int o = blockIdx.x, t = threadIdx.x;   // 128 blocks x 32 threads
    g_acc[o*32 + t] = 0.f;
    float s = 0.f;
    for (int k = t; k < PD; k += 32) s += w[o*PD + k];
    #pragma unroll
    for (int off = 16; off; off >>= 1) s += __shfl_xor_sync(0xffffffffu, s, off);
    if (t == 0) g_const2[o] = b[o] + CENTER * s;
}

// ---- pass 1: LPPool3d + center + bf16, float4 loads, channel-last via smem transpose ----
__global__ __launch_bounds__(128) void pool_kernel(const float* __restrict__ x) {
    __shared__ __nv_bfloat16 s2[128*18];   // [w][mc], stride 18 for bank spread
    const int task = blockIdx.x;           // (n, h)
    const int n = task >> 7, h = task & 127;
    const int t = threadIdx.x;
    const int wp = t & 63;                 // w-pair
    const int mh = t >> 6;                 // channel half

    const float* xb = x + (size_t)n*8*4*65536 + 2*h*256 + 4*wp;
    #pragma unroll
    for (int q = 0; q < 8; q++) {
        int mc = mh*8 + q;
        int dp = mc >> 3, c = mc & 7;
        const float* base = xb + (size_t)(c*4 + 2*dp)*65536;
        float4 r0 = *(const float4*)(base);
        float4 r1 = *(const float4*)(base + 256);
        float4 r2 = *(const float4*)(base + 65536);
        float4 r3 = *(const float4*)(base + 65536 + 256);
        float a0 = r0.x*r0.x + r0.y*r0.y + r1.x*r1.x + r1.y*r1.y
                 + r2.x*r2.x + r2.y*r2.y + r3.x*r3.x + r3.y*r3.y;
        float a1 = r0.z*r0.z + r0.w*r0.w + r1.z*r1.z + r1.w*r1.w
                 + r2.z*r2.z + r2.w*r2.w + r3.z*r3.z + r3.w*r3.w;
        s2[(2*wp)*18 + mc]   = __float2bfloat16(sqrtf(a0) - CENTER);
        s2[(2*wp+1)*18 + mc] = __float2bfloat16(sqrtf(a1) - CENTER);
    }
    __syncthreads();
    // channel-last writeback: thread t -> row w = t (32 contiguous bytes)
    uint32_t v[8];
    #pragma unroll
    for (int k = 0; k < 8; k++)
        v[k] = *(const uint32_t*)(s2 + t*18 + 2*k);
    __nv_bfloat16* dst = g_pooled + (size_t)((n*HP + h)*WPD + t)*MCH;
    *(uint4*)(dst)     = make_uint4(v[0], v[1], v[2], v[3]);
    *(uint4*)(dst + 8) = make_uint4(v[4], v[5], v[6], v[7]);
}

// ---- pass 2: persistent mma.sync implicit-conv GEMM over 512-patch windows (R13) ----
__global__ __launch_bounds__(256, 1) void gemm_kernel(const float* __restrict__ w) {
    extern __shared__ __align__(16) unsigned char smem[];
    uint32_t aS = smem_u32(smem);
    const uint32_t aZ = aS + 2*WIN_BYTES;   // 16B zero block

    const int tid = threadIdx.x, warp = tid >> 5, lane = tid & 31;
    const int wm = warp & 3, wn = warp >> 2;   // 4 o-tiles x 2 l-halves
    const int g  = lane >> 2, th = lane & 3;
    const int obase = wm * 32;
    const int lbase = wn * 64;
    const uint32_t hf16 = ((lane >> 3) & 1) * 16;
    const int rowoff = (lane & 7) + ((lane >> 4) << 3);

    // ---- stage W (temp, overlaps window region), preload A fragments ----
    {
        __nv_bfloat16* sW = (__nv_bfloat16*)smem;
        for (int t = tid; t < OD*PD; t += 256) {
            int o = t / PD, kp = t - o*PD;
            int sft = kp >> 4, c = kp & 15;
            sW[o*WS + kp] = __float2bfloat16(w[o*PD + c*9 + sft]);
        }
    }
    __syncthreads();
    uint32_t Afr[2][9][4];
    {
        uint32_t aA0 = aS + (obase + (lane & 15)) * (WS*2) + (lane >> 4) * 16;
        #pragma unroll
        for (int mt = 0; mt < 2; mt++)
            #pragma unroll
            for (int s = 0; s < 9; s++)
                ldsm_x4(Afr[mt][s], aA0 + mt*16*(WS*2) + s*32);
    }
    float cst[2][2];
    #pragma unroll
    for (int mt = 0; mt < 2; mt++) {
        cst[mt][0] = g_const2[obase + mt*16 + g];
        cst[mt][1] = g_const2[obase + mt*16 + g + 8];
    }
    if (tid == 0) *(uint4*)(smem + 2*WIN_BYTES) = make_uint4(0u, 0u, 0u, 0u);
    __syncthreads();   // A frags read + zero block ready; windows may now be written

    // staging: thread handles row k (0..7) at 16B chunk tid (XOR-16 swizzle)
    const uint32_t sdst_base = aS + ((uint32_t)(tid*16) ^ (uint32_t)((tid & 8) << 1));
    const __nv_bfloat16* srcb = g_pooled + tid*8;

    // ---- stage first window ----
    int idx = blockIdx.x;
    {
        int n = idx >> 5, tile = idx & 31;
        int pi0 = (tile << 9) / 126;
        #pragma unroll
        for (int r = 0; r < WIN_ROWS; r++) {
            int grow = pi0 + r; if (grow > 127) grow = 127;
            cp16(sdst_base + r*4096, srcb + (n*HP + grow)*WPD*MCH);
        }
        asm volatile("cp.async.commit_group;" ::: "memory");
    }

    uint32_t boff = 0;
    for (; idx < NTILES; idx += GRID_GEMM) {
        asm volatile("cp.async.wait_group 0;" ::: "memory");
        __syncthreads();   // current window ready; previous window's readers done

        int n = idx >> 5, tile = idx & 31;
        int l0 = tile << 9;
        int pi0 = l0 / 126;

        // stage next window into other buffer (overlapped with compute)
        int nidx = idx + GRID_GEMM;
        if (nidx < NTILES) {
            int nn = nidx >> 5, ntile = nidx & 31;
            int npi0 = (ntile << 9) / 126;
            uint32_t d = sdst_base + (boff ^ WIN_BYTES);
            #pragma unroll
            for (int r = 0; r < WIN_ROWS; r++) {
                int grow = npi0 + r; if (grow > 127) grow = 127;
                cp16(d + r*4096, srcb + (nn*HP + grow)*WPD*MCH);
            }
        }
        asm volatile("cp.async.commit_group;" ::: "memory");

        const uint32_t wbase = aS + boff;
        float rs[2][2] = {{0.f, 0.f}, {0.f, 0.f}};

        #pragma unroll
        for (int sub = 0; sub < 4; sub++) {
            // per-fragment lane row bases within the window
            uint32_t pb[4]; bool pv[4];
            #pragma unroll
            for (int p = 0; p < 4; p++) {
                int lg = l0 + sub*128 + lbase + p*16 + rowoff;
                unsigned pi = (unsigned)lg / 126u;
                unsigned pj = (unsigned)lg - pi*126u;
                pv[p] = lg < LTOT;
                pb[p] = (pi - (unsigned)pi0)*4096u + pj*32u + hf16;
            }

            float acc[2][8][4];
            #pragma unroll
            for (int mt = 0; mt < 2; mt++)
                #pragma unroll
                for (int nf = 0; nf < 8; nf++)
                    #pragma unroll
                    for (int q = 0; q < 4; q++) acc[mt][nf][q] = 0.f;

            #pragma unroll
            for (int s = 0; s < 9; s++) {
                const int ki = s / 3, kj = s - 3*ki;
                const uint32_t ko = ki*4096u + kj*32u;
                #pragma unroll
                for (int p = 0; p < 4; p++) {
                    uint32_t rel = pb[p] + ko;
                    rel ^= (rel >> 3) & 0x10u;      // bank de-conflict swizzle
                    uint32_t a = pv[p] ? (wbase + rel) : aZ;
                    uint32_t bb[4];
                    ldsm_x4(bb, a);
                    mma16816(acc[0][2*p],   Afr[0][s], bb[0], bb[1]);
                    mma16816(acc[0][2*p+1], Afr[0][s], bb[2], bb[3]);
                    mma16816(acc[1][2*p],   Afr[1][s], bb[0], bb[1]);
                    mma16816(acc[1][2*p+1], Afr[1][s], bb[2], bb[3]);
                }
            }

            // branch-free celu sums (pad corrected analytically in norm)
            #pragma unroll
            for (int mt = 0; mt < 2; mt++) {
                float s0 = 0.f, s1 = 0.f, e0 = 0.f, e1 = 0.f;
                #pragma unroll
                for (int nf = 0; nf < 8; nf++) {
                    #pragma unroll
                    for (int cc = 0; cc < 2; cc++) {
                        float v = acc[mt][nf][cc] + cst[mt][0];
                        s0 += fmaxf(v, 0.f);
                        e0 += __expf(fminf(v, 0.f));
                        float u = acc[mt][nf][2 + cc] + cst[mt][1];
                        s1 += fmaxf(u, 0.f);
                        e1 += __expf(fminf(u, 0.f));
                    }
                }
                rs[mt][0] += s0 + e0;
                rs[mt][1] += s1 + e1;
            }
        }

        #pragma unroll
        for (int mt = 0; mt < 2; mt++) {
            float s0 = rs[mt][0], s1 = rs[mt][1];
            #pragma unroll
            for (int off = 1; off < 4; off <<= 1) {
                s0 += __shfl_xor_sync(0xffffffffu, s0, off);
                s1 += __shfl_xor_sync(0xffffffffu, s1, off);
            }
            if (th == 0) {
                atomicAdd(&g_acc[n*OD + obase + mt*16 + g],     s0);
                atomicAdd(&g_acc[n*OD + obase + mt*16 + g + 8], s1);
            }
        }
        boff ^= WIN_BYTES;
    }
}

// ---- pass 3: pad-correct + mean + clamped L2 normalize ----
__global__ void norm_kernel(float* __restrict__ out) {
    int n = blockIdx.x, o = threadIdx.x;
    float cst = g_const2[o];
    float padv = fmaxf(cst, 0.f) + __expf(fminf(cst, 0.f));  // per padded slot (no -1)
    float a = (g_acc[n*OD + o] - (float)PAD_PER_N * padv - (float)LTOT) * (1.f / (float)LTOT);
    float ss = a * a;
    __shared__ float red[4];
    int lane = o & 31, w = o >> 5;
    #pragma unroll
    for (int off = 16; off; off >>= 1) ss += __shfl_xor_sync(0xffffffffu, ss, off);
    if (lane == 0) red[w] = ss;
    __syncthreads();
    float norm = sqrtf(red[0] + red[1] + red[2] + red[3]);
    out[n*OD + o] = a / fmaxf(norm, 1e-6f);
}

// ---- launch ----
extern "C" void kernel_launch(void* const* d_in, const int* in_sizes, int n_in,
                              void* d_out, int out_size) {
    const float* x = (const float*)d_in[0];
    const float* w = (const float*)d_in[1];
    const float* b = (const float*)d_in[2];
    float* out = (float*)d_out;

    prep_kernel<<<128, 32>>>(w, b);
    pool_kernel<<<NPTASK, 128>>>(x);
    cudaFuncSetAttribute(gemm_kernel, cudaFuncAttributeMaxDynamicSharedMemorySize, SMEM_BYTES);
    gemm_kernel<<<GRID_GEMM, 256, SMEM_BYTES>>>(w);
    norm_kernel<<<NB, 128>>>(out);
}